// round 9
// baseline (speedup 1.0000x reference)
#include <cuda_runtime.h>
#include <cstdint>

// Problem constants (K_Rectify): B=128, NTOT=129, N=128, GS=16, C=384
#define PB    128
#define PNTOT 129
#define PN    128
#define PGS   16
#define PC    384
#define EPSW  0.05f
#define RMSE  1e-6f

#define WARPS_PER_CTA 8
#define NPTS  (PB * PN)            // 16384 compute points
#define NWARP (NPTS + PB)          // + 128 cls-copy warps = 16512

// One warp per point. Each lane owns float4 columns {lane, lane+32, lane+64}
// of the 384-float row. No shared memory, no __syncthreads.
__global__ void __launch_bounds__(WARPS_PER_CTA * 32)
k_rectify_kernel(const float* __restrict__ f,
                 const float* __restrict__ dist,
                 const float* __restrict__ rf,
                 const float* __restrict__ knw,
                 const int* __restrict__ idx,
                 float* __restrict__ out)
{
    const int w    = blockIdx.x * WARPS_PER_CTA + (threadIdx.x >> 5);
    const int lane = threadIdx.x & 31;

    if (w >= NPTS) {
        // cls-token copy: out[b, 0, :] = f[b, 0, :]
        const int b = w - NPTS;
        const float4* src = reinterpret_cast<const float4*>(f  + (size_t)b * PNTOT * PC);
        float4*       dst = reinterpret_cast<float4*>(out + (size_t)b * PNTOT * PC);
        dst[lane]      = src[lane];
        dst[lane + 32] = src[lane + 32];
        dst[lane + 64] = src[lane + 64];
        return;
    }

    // ---- per-point weights + gather offsets (lanes 0-15), register-resident ----
    float wv = 0.f;
    int   off = 0;
    if (lane < PGS) {
        const float d = dist[w * PGS + lane];
        wv = 1.0f / (d + EPSW);
        const int j = idx[w * PGS + lane];          // j in [0, B*N)
        off = ((j >> 7) * PNTOT + 1 + (j & (PN - 1))) * PC;
    }
    float s = wv;
    #pragma unroll
    for (int o = 8; o > 0; o >>= 1)
        s += __shfl_xor_sync(0xFFFFFFFFu, s, o, 16);
    wv = wv / s;                                    // lanes >= 16: garbage, never read

    // ---- x row; accumulators start at -x (weights sum to 1) ----
    const int xoff = ((w >> 7) * PNTOT + 1 + (w & (PN - 1))) * PC;
    const float4* xr = reinterpret_cast<const float4*>(f + (size_t)xoff);
    const float4 xa = xr[lane];
    const float4 xb = xr[lane + 32];
    const float4 xc = xr[lane + 64];

    float a0 = -xa.x, a1 = -xa.y, a2 = -xa.z, a3 = -xa.w;
    float b0 = -xb.x, b1 = -xb.y, b2 = -xb.z, b3 = -xb.w;
    float c0 = -xc.x, c1 = -xc.y, c2 = -xc.z, c3 = -xc.w;

    // ---- weighted neighbor gather: 16 rows x 3 LDG.128 per lane ----
    #pragma unroll
    for (int g = 0; g < PGS; g++) {
        const float wg = __shfl_sync(0xFFFFFFFFu, wv, g);
        const int   og = __shfl_sync(0xFFFFFFFFu, off, g);
        const float4* r = reinterpret_cast<const float4*>(f + (size_t)og);
        const float4 n0 = r[lane];
        const float4 n1 = r[lane + 32];
        const float4 n2 = r[lane + 64];
        a0 = fmaf(wg, n0.x, a0); a1 = fmaf(wg, n0.y, a1);
        a2 = fmaf(wg, n0.z, a2); a3 = fmaf(wg, n0.w, a3);
        b0 = fmaf(wg, n1.x, b0); b1 = fmaf(wg, n1.y, b1);
        b2 = fmaf(wg, n1.z, b2); b3 = fmaf(wg, n1.w, b3);
        c0 = fmaf(wg, n2.x, c0); c1 = fmaf(wg, n2.y, c1);
        c2 = fmaf(wg, n2.z, c2); c3 = fmaf(wg, n2.w, c3);
    }

    // ---- RMS over the 384-channel row (32-lane butterfly) ----
    float ss = a0*a0 + a1*a1 + a2*a2 + a3*a3
             + b0*b0 + b1*b1 + b2*b2 + b3*b3
             + c0*c0 + c1*c1 + c2*c2 + c3*c3;
    #pragma unroll
    for (int o = 16; o > 0; o >>= 1)
        ss += __shfl_xor_sync(0xFFFFFFFFu, ss, o);
    const float inv = rsqrtf(ss * (1.0f / PC) + RMSE);

    // ---- out = rf[1+n] + x + (sf * inv) * knorm_w ----
    const int n = w & (PN - 1);
    const float4* rr = reinterpret_cast<const float4*>(rf + (size_t)(1 + n) * PC);
    const float4* kk = reinterpret_cast<const float4*>(knw);
    float4* op = reinterpret_cast<float4*>(out + (size_t)xoff);

    float4 o4;
    const float4 r0 = rr[lane],      k0 = kk[lane];
    o4.x = r0.x + xa.x + a0 * inv * k0.x;
    o4.y = r0.y + xa.y + a1 * inv * k0.y;
    o4.z = r0.z + xa.z + a2 * inv * k0.z;
    o4.w = r0.w + xa.w + a3 * inv * k0.w;
    op[lane] = o4;

    const float4 r1 = rr[lane + 32], k1 = kk[lane + 32];
    o4.x = r1.x + xb.x + b0 * inv * k1.x;
    o4.y = r1.y + xb.y + b1 * inv * k1.y;
    o4.z = r1.z + xb.z + b2 * inv * k1.z;
    o4.w = r1.w + xb.w + b3 * inv * k1.w;
    op[lane + 32] = o4;

    const float4 r2 = rr[lane + 64], k2 = kk[lane + 64];
    o4.x = r2.x + xc.x + c0 * inv * k2.x;
    o4.y = r2.y + xc.y + c1 * inv * k2.y;
    o4.z = r2.z + xc.z + c2 * inv * k2.z;
    o4.w = r2.w + xc.w + c3 * inv * k2.w;
    op[lane + 64] = o4;
}

extern "C" void kernel_launch(void* const* d_in, const int* in_sizes, int n_in,
                              void* d_out, int out_size)
{
    const float* f    = (const float*)d_in[0];
    const float* dist = (const float*)d_in[1];
    const float* rf   = (const float*)d_in[2];
    const float* knw  = (const float*)d_in[3];
    const int*   idx  = (const int*)d_in[4];
    float*       out  = (float*)d_out;

    const int grid = (NWARP + WARPS_PER_CTA - 1) / WARPS_PER_CTA;  // 2064
    k_rectify_kernel<<<grid, WARPS_PER_CTA * 32>>>(f, dist, rf, knw, idx, out);
}

// round 10
// speedup vs baseline: 1.2246x; 1.2246x over previous
#include <cuda_runtime.h>
#include <cuda_fp16.h>
#include <cstdint>

// Problem constants (K_Rectify): B=128, NTOT=129, N=128, GS=16, C=384
#define PB    128
#define PNTOT 129
#define PN    128
#define PGS   16
#define PC    384
#define EPSW  0.05f
#define RMSE  1e-6f

#define NPTS (PB * PN)   // 16384

// fp16 staging of the gatherable point rows f[:,1:,:], indexed directly by idx value.
// 16384 rows x 384 halves = 12.58 MB. Static __device__ scratch (no allocation).
__device__ __align__(16) __half2 g_half[(size_t)NPTS * (PC / 2)];

// ---------------- Kernel 1: fp32 -> fp16 staging ----------------
// One float4 (4 channels) per thread. 6.29M elements / 4 = 1,572,864 threads.
__global__ void __launch_bounds__(256)
k_convert_kernel(const float* __restrict__ f)
{
    const int t = blockIdx.x * blockDim.x + threadIdx.x;   // float4 slot
    const int r  = t / (PC / 4);                           // point row 0..16383
    const int c4 = t - r * (PC / 4);                       // float4 column 0..95

    const float4 v = reinterpret_cast<const float4*>(
        f + (size_t)((r >> 7) * PNTOT + 1 + (r & (PN - 1))) * PC)[c4];

    const __half2 h0 = __floats2half2_rn(v.x, v.y);
    const __half2 h1 = __floats2half2_rn(v.z, v.w);
    uint2 u;
    u.x = *reinterpret_cast<const unsigned*>(&h0);
    u.y = *reinterpret_cast<const unsigned*>(&h1);
    reinterpret_cast<uint2*>(g_half + (size_t)r * (PC / 2))[c4] = u;
}

// ---------------- Kernel 2: rectify (R8 structure, fp16 gather) ----------------
// 96 threads per CTA, one point per CTA; thread t owns channels [4t, 4t+4).
// Blocks [0, B*N): compute; blocks [B*N, B*N+B): cls-token copy.
__global__ void __launch_bounds__(96, 17)
k_rectify_kernel(const float* __restrict__ f,
                 const float* __restrict__ dist,
                 const float* __restrict__ rf,
                 const float* __restrict__ knw,
                 const int* __restrict__ idx,
                 float* __restrict__ out)
{
    const int p   = blockIdx.x;
    const int tid = threadIdx.x;

    if (p >= NPTS) {
        const int b = p - NPTS;
        const float4* src = reinterpret_cast<const float4*>(f  + (size_t)b * PNTOT * PC);
        float4*       dst = reinterpret_cast<float4*>(out + (size_t)b * PNTOT * PC);
        dst[tid] = src[tid];
        return;
    }

    const int b = p >> 7;
    const int n = p & (PN - 1);

    __shared__ float sw[PGS];      // normalized weights
    __shared__ int   sj[PGS];      // gather row index (into g_half)
    __shared__ float sred[3];      // per-warp RMS partials

    if (tid < PGS) {
        const float d = dist[p * PGS + tid];
        float wv = 1.0f / (d + EPSW);
        float s  = wv;
        #pragma unroll
        for (int o = 8; o > 0; o >>= 1)
            s += __shfl_xor_sync(0x0000FFFFu, s, o, 16);
        sw[tid] = wv / s;
        sj[tid] = idx[p * PGS + tid];   // j in [0, B*N) — direct row into g_half
    }
    __syncthreads();

    // x row (fp32, exact); accumulators start at -x (weights sum to 1)
    const int xoff = (b * PNTOT + 1 + n) * PC;
    const float4 x4 = reinterpret_cast<const float4*>(f + (size_t)xoff)[tid];
    float a0 = -x4.x, a1 = -x4.y, a2 = -x4.z, a3 = -x4.w;

    // Weighted gather from fp16 staging: 16 x LDG.64 per thread
    #pragma unroll
    for (int g = 0; g < PGS; g++) {
        const uint2 v = reinterpret_cast<const uint2*>(
            g_half + (size_t)sj[g] * (PC / 2))[tid];
        const float wg = sw[g];
        const float2 f0 = __half22float2(*reinterpret_cast<const __half2*>(&v.x));
        const float2 f1 = __half22float2(*reinterpret_cast<const __half2*>(&v.y));
        a0 = fmaf(wg, f0.x, a0);
        a1 = fmaf(wg, f0.y, a1);
        a2 = fmaf(wg, f1.x, a2);
        a3 = fmaf(wg, f1.y, a3);
    }

    // RMS over the 384-channel row
    float ss = a0 * a0 + a1 * a1 + a2 * a2 + a3 * a3;
    #pragma unroll
    for (int o = 16; o > 0; o >>= 1)
        ss += __shfl_xor_sync(0xFFFFFFFFu, ss, o);
    if ((tid & 31) == 0) sred[tid >> 5] = ss;
    __syncthreads();
    const float tot = sred[0] + sred[1] + sred[2];
    const float inv = rsqrtf(tot * (1.0f / PC) + RMSE);

    // out = rf[1+n] + x + (sf * inv) * knorm_w
    const float4 r4 = reinterpret_cast<const float4*>(rf + (size_t)(1 + n) * PC)[tid];
    const float4 k4 = reinterpret_cast<const float4*>(knw)[tid];

    float4 o4;
    o4.x = r4.x + x4.x + a0 * inv * k4.x;
    o4.y = r4.y + x4.y + a1 * inv * k4.y;
    o4.z = r4.z + x4.z + a2 * inv * k4.z;
    o4.w = r4.w + x4.w + a3 * inv * k4.w;
    reinterpret_cast<float4*>(out + (size_t)xoff)[tid] = o4;
}

extern "C" void kernel_launch(void* const* d_in, const int* in_sizes, int n_in,
                              void* d_out, int out_size)
{
    const float* f    = (const float*)d_in[0];
    const float* dist = (const float*)d_in[1];
    const float* rf   = (const float*)d_in[2];
    const float* knw  = (const float*)d_in[3];
    const int*   idx  = (const int*)d_in[4];
    float*       out  = (float*)d_out;

    // Stage f[:,1:,:] as fp16 rows, then rectify.
    const int conv_threads = NPTS * (PC / 4);              // 1,572,864
    k_convert_kernel<<<conv_threads / 256, 256>>>(f);

    const int grid = NPTS + PB;                            // 16384 + 128 cls blocks
    k_rectify_kernel<<<grid, 96>>>(f, dist, rf, knw, idx, out);
}